// round 12
// baseline (speedup 1.0000x reference)
#include <cuda_runtime.h>
#include <cuda_bf16.h>
#include <cstdint>

// Problem constants
#define B_      32
#define C_      3
#define H_      257
#define W_      257
#define STRIDE_ 4
#define NW_     61                 // windows per axis
#define WSZ_    289                // 17*17
#define PLANE_  (257*257)          // 66049
#define SW_ELEMS  ((long long)357216 * WSZ_)       // 103,235,424
#define S_ELEMS   ((long long)B_ * 12 * NW_ * NW_) // 1,428,864
#define S_OFF     SW_ELEMS
#define Q_OFF     (SW_ELEMS + S_ELEMS)             // 104,664,288

#define JT_       8                 // windows per copy block (along j)
#define NIQ_      16                // ceil(61/4) i-quads
#define TILE_COLS 45                // (JT_-1)*4 + 17
#define TILE_PAD  48                // padded row stride (R10 champion value)
#define TILE_ROWS 29                // covers i0..i0+3 (rows 0..16 / 4..20 / 8..24 / 12..28)
#define TILE_N    (TILE_ROWS * TILE_COLS)  // 1305
#define SBUF_N    (TILE_ROWS * TILE_PAD)   // 1392 >= stats 4*257=1028

// One kernel, two block roles, interleaved 8:4 per (bc, i-quad).
// Copy block: 29x45 x-tile staged once, each warp runs the window body for
// i0..i0+3 at its j -> 32 windows/block (30% less staging per window vs R10).
// Stats blocks (4 per group) compute separable window stats -> s.
__global__ __launch_bounds__(256, 8) void leafnet_kernel(
    const float* __restrict__ x, float* __restrict__ out)
{
    __shared__ float sbuf[SBUF_N];

    const int sl  = blockIdx.x % 12;           // 0..7 copy jt, 8..11 stats
    const int grp = blockIdx.x / 12;
    const int iq  = grp % NIQ_;
    const int bc  = grp / NIQ_;                // b*3 + c
    const int i0  = iq * 4;

    if (sl >= 8) {
        // ================= Stats role: separable window stats -> s ==========
        const int i = i0 + (sl - 8);
        if (i >= NW_) return;
        const float* xrow = x + (size_t)bc * PLANE_ + (size_t)(i * STRIDE_) * W_;
        float* vs  = sbuf;
        float* vq  = sbuf + W_;
        float* vmn = sbuf + 2 * W_;
        float* vmx = sbuf + 3 * W_;

        for (int c = threadIdx.x; c < W_; c += 256) {
            float s = 0.0f, q = 0.0f, mn = 1e30f, mx = -1e30f;
            #pragma unroll
            for (int u = 0; u < 17; u++) {
                const float v = __ldg(xrow + u * W_ + c);
                s += v; q = fmaf(v, v, q);
                mn = fminf(mn, v); mx = fmaxf(mx, v);
            }
            vs[c] = s; vq[c] = q; vmn[c] = mn; vmx[c] = mx;
        }
        __syncthreads();

        const int j = threadIdx.x;
        if (j < NW_) {
            float s = 0.0f, q = 0.0f, mn = 1e30f, mx = -1e30f;
            #pragma unroll
            for (int k = 0; k < 17; k++) {
                const int c = 4 * j + k;
                s += vs[c]; q += vq[c];
                mn = fminf(mn, vmn[c]); mx = fmaxf(mx, vmx[c]);
            }
            const float inv  = 1.0f / 289.0f;
            const float mean = s * inv;
            const float var  = fmaxf(q * inv - mean * mean, 0.0f);
            const float stdv = sqrtf(var);

            const int b  = bc / 3;
            const int c0 = bc - b * 3;
            const int pos = i * NW_ + j;
            float* sp = out + (size_t)S_OFF + (size_t)b * 12 * (NW_ * NW_);
            // layout: [ (max-0.5)*4 | std*4 | (max-mean)*4 | (mean-min)*4 ] x C
            sp[(0 * 3 + c0) * (NW_ * NW_) + pos] = (mx - 0.5f) * 4.0f;
            sp[(1 * 3 + c0) * (NW_ * NW_) + pos] = stdv * 4.0f;
            sp[(2 * 3 + c0) * (NW_ * NW_) + pos] = (mx - mean) * 4.0f;
            sp[(3 * 3 + c0) * (NW_ * NW_) + pos] = (mean - mn) * 4.0f;
        }
        return;
    }

    // ================= Copy role: gather-copy + quantize, 4 i's per block ====
    float* tile = sbuf;                        // 29 x TILE_PAD
    const int jt = sl;
    const int j0 = jt * JT_;

    {   // Cooperative coalesced tile load: rows [4i0, 4i0+29), cols [4j0, 4j0+45)
        const float* xbase = x + (size_t)bc * PLANE_ + (size_t)(i0 * STRIDE_) * W_;
        const int cbase = j0 * STRIDE_;
        const int rbase = i0 * STRIDE_;
        #pragma unroll
        for (int p = 0; p < 6; p++) {
            const int idx = threadIdx.x + p * 256;   // 1305 valid
            if (idx < TILE_N) {
                const int r  = idx / TILE_COLS;
                const int c  = idx - r * TILE_COLS;
                const int gc = cbase + c;
                const bool ok = (rbase + r < H_) && (gc < W_);
                tile[r * TILE_PAD + c] = ok ? __ldg(xbase + r * W_ + gc) : 0.0f;
            }
        }
    }
    __syncthreads();

    const int w    = threadIdx.x >> 5;          // window slot (0..7)
    const int lane = threadIdx.x & 31;
    const int j    = j0 + w;
    if (j >= NW_) return;                       // only last jt loses warps 5..7

    #pragma unroll 1
    for (int ii = 0; ii < 4; ii++) {
        const int i = i0 + ii;
        if (i >= NW_) break;                    // last quad has only i=60

        const int wid = (bc * NW_ + i) * NW_ + j;
        const float* wsm = tile + ii * STRIDE_ * TILE_PAD + w * STRIDE_;
        float* swp = out + (size_t)wid * WSZ_;
        float* qp  = out + (size_t)Q_OFF + (size_t)wid * WSZ_;

        const int a         = (-wid) & 3;       // head count to reach 16B alignment
        const int ngroups   = (WSZ_ - a) >> 2;  // 71 or 72 float4 groups
        const int tailstart = a + (ngroups << 2);
        const int tail      = WSZ_ - tailstart; // 0..3

        auto doScalar = [&](int e) {
            const int u = (e * 241) >> 12;      // e / 17 (exact for 0<=e<=288)
            const int v = e - u * 17;
            const float val = wsm[u * TILE_PAD + v];
            __stcs(swp + e, val);
            __stcs(qp  + e, floorf(val * 64.0f)); // digitize(linspace(0,1,65)) - 1
        };

        auto doGroup = [&](int e0) {            // e0 16B-aligned within out
            float wv[4];
            #pragma unroll
            for (int tt = 0; tt < 4; tt++) {
                const int e = e0 + tt;
                const int u = (e * 241) >> 12;
                const int v = e - u * 17;
                wv[tt] = wsm[u * TILE_PAD + v];
            }
            __stcs(reinterpret_cast<float4*>(swp + e0),
                   make_float4(wv[0], wv[1], wv[2], wv[3]));
            __stcs(reinterpret_cast<float4*>(qp + e0),
                   make_float4(floorf(wv[0] * 64.0f), floorf(wv[1] * 64.0f),
                               floorf(wv[2] * 64.0f), floorf(wv[3] * 64.0f)));
        };

        if (lane < a) doScalar(lane);
        doGroup(a + 4 * lane);                  // lane      < 71 <= ngroups : always
        doGroup(a + 4 * (lane + 32));           // lane + 32 < 64 < 71      : always
        if (lane + 64 < ngroups) doGroup(a + 4 * (lane + 64));   // 7-8 lanes
        if (lane < tail) doScalar(tailstart + lane);
    }
}

extern "C" void kernel_launch(void* const* d_in, const int* in_sizes, int n_in,
                              void* d_out, int out_size)
{
    const float* x = (const float*)d_in[0];   // (32,3,257,257) float32
    // d_in[1] = bins (65 floats) — uniform linspace(0,1,65); digitize-1 == floor(v*64)
    float* out = (float*)d_out;

    // 12 blocks per (bc, i-quad): 8 copy j-tiles (4 i's each) + 4 stats
    const int blocks = (B_ * C_) * NIQ_ * 12;  // 96 * 16 * 12 = 18432
    leafnet_kernel<<<blocks, 256>>>(x, out);
}

// round 13
// speedup vs baseline: 1.2013x; 1.2013x over previous
#include <cuda_runtime.h>
#include <cuda_bf16.h>
#include <cstdint>

// Problem constants
#define B_      32
#define C_      3
#define H_      257
#define W_      257
#define STRIDE_ 4
#define NW_     61                 // windows per axis
#define WSZ_    289                // 17*17
#define PLANE_  (257*257)          // 66049
#define SW_ELEMS  ((long long)357216 * WSZ_)       // 103,235,424
#define S_ELEMS   ((long long)B_ * 12 * NW_ * NW_) // 1,428,864
#define S_OFF     SW_ELEMS
#define Q_OFF     (SW_ELEMS + S_ELEMS)             // 104,664,288

#define JT_       8                 // windows per copy block (along j)
#define NIP_      31                // ceil(61/2) i-pairs
#define TILE_COLS 45                // (JT_-1)*4 + 17
#define TILE_PAD  48                // padded row stride (champion value)
#define TILE_ROWS 21                // covers i0 (rows 0..16) and i0+1 (rows 4..20)
#define TILE_N    (TILE_ROWS * TILE_COLS)  // 945
#define SBUF_N    1056              // max(21*48=1008 copy tile, 4*257=1028 stats)

// R10 champion structure: one kernel, two block roles, interleaved 8:2 per
// (bc, i-pair). Copy block: 21x45 x-tile staged once; each warp runs the
// window body for (i0, j) then (i0+1, j). Delta vs R10: the two unconditional
// float4 groups are merged, stores reordered per-stream (sw,sw,q,q) for
// contiguous 1KB warp bursts per stream; interior blocks take an unguarded
// tile-load fast path.
__global__ __launch_bounds__(256, 8) void leafnet_kernel(
    const float* __restrict__ x, float* __restrict__ out)
{
    __shared__ float sbuf[SBUF_N];

    const int sl  = blockIdx.x % 10;           // 0..7 copy jt, 8..9 stats
    const int grp = blockIdx.x / 10;
    const int ip  = grp % NIP_;
    const int bc  = grp / NIP_;                // b*3 + c
    const int i0  = ip * 2;

    if (sl >= 8) {
        // ================= Stats role: separable window stats -> s ==========
        const int i = i0 + (sl - 8);
        if (i >= NW_) return;
        const float* xrow = x + (size_t)bc * PLANE_ + (size_t)(i * STRIDE_) * W_;
        float* vs  = sbuf;
        float* vq  = sbuf + W_;
        float* vmn = sbuf + 2 * W_;
        float* vmx = sbuf + 3 * W_;

        for (int c = threadIdx.x; c < W_; c += 256) {
            float s = 0.0f, q = 0.0f, mn = 1e30f, mx = -1e30f;
            #pragma unroll
            for (int u = 0; u < 17; u++) {
                const float v = __ldg(xrow + u * W_ + c);
                s += v; q = fmaf(v, v, q);
                mn = fminf(mn, v); mx = fmaxf(mx, v);
            }
            vs[c] = s; vq[c] = q; vmn[c] = mn; vmx[c] = mx;
        }
        __syncthreads();

        const int j = threadIdx.x;
        if (j < NW_) {
            float s = 0.0f, q = 0.0f, mn = 1e30f, mx = -1e30f;
            #pragma unroll
            for (int k = 0; k < 17; k++) {
                const int c = 4 * j + k;
                s += vs[c]; q += vq[c];
                mn = fminf(mn, vmn[c]); mx = fmaxf(mx, vmx[c]);
            }
            const float inv  = 1.0f / 289.0f;
            const float mean = s * inv;
            const float var  = fmaxf(q * inv - mean * mean, 0.0f);
            const float stdv = sqrtf(var);

            const int b  = bc / 3;
            const int c0 = bc - b * 3;
            const int pos = i * NW_ + j;
            float* sp = out + (size_t)S_OFF + (size_t)b * 12 * (NW_ * NW_);
            // layout: [ (max-0.5)*4 | std*4 | (max-mean)*4 | (mean-min)*4 ] x C
            sp[(0 * 3 + c0) * (NW_ * NW_) + pos] = (mx - 0.5f) * 4.0f;
            sp[(1 * 3 + c0) * (NW_ * NW_) + pos] = stdv * 4.0f;
            sp[(2 * 3 + c0) * (NW_ * NW_) + pos] = (mx - mean) * 4.0f;
            sp[(3 * 3 + c0) * (NW_ * NW_) + pos] = (mean - mn) * 4.0f;
        }
        return;
    }

    // ================= Copy role: gather-copy + quantize, 2 i's per block ====
    float* tile = sbuf;                        // 21 x TILE_PAD
    const int jt = sl;
    const int j0 = jt * JT_;

    {   // Cooperative coalesced tile load: rows [4i0, 4i0+21), cols [4j0, 4j0+45)
        const float* xbase = x + (size_t)bc * PLANE_ + (size_t)(i0 * STRIDE_) * W_;
        const int cbase = j0 * STRIDE_;
        const int rbase = i0 * STRIDE_;
        if (rbase + TILE_ROWS <= H_ && cbase + TILE_COLS <= W_) {
            // interior fast path: no guards
            #pragma unroll
            for (int p = 0; p < 4; p++) {
                const int idx = threadIdx.x + p * 256;
                if (idx < TILE_N) {
                    const int r = idx / TILE_COLS;
                    const int c = idx - r * TILE_COLS;
                    tile[r * TILE_PAD + c] = __ldg(xbase + r * W_ + c + cbase);
                }
            }
        } else {
            #pragma unroll
            for (int p = 0; p < 4; p++) {
                const int idx = threadIdx.x + p * 256;
                if (idx < TILE_N) {
                    const int r  = idx / TILE_COLS;
                    const int c  = idx - r * TILE_COLS;
                    const int gc = cbase + c;
                    const bool ok = (rbase + r < H_) && (gc < W_);
                    tile[r * TILE_PAD + c] = ok ? __ldg(xbase + r * W_ + gc) : 0.0f;
                }
            }
        }
    }
    __syncthreads();

    const int w    = threadIdx.x >> 5;          // window slot (0..7)
    const int lane = threadIdx.x & 31;
    const int j    = j0 + w;
    if (j >= NW_) return;                       // only last jt loses warps 5..7

    #pragma unroll 1
    for (int ii = 0; ii < 2; ii++) {
        const int i = i0 + ii;
        if (i >= NW_) break;                    // i0=60 pair has no second i

        const int wid = (bc * NW_ + i) * NW_ + j;
        const float* wsm = tile + ii * STRIDE_ * TILE_PAD + w * STRIDE_;
        float* swp = out + (size_t)wid * WSZ_;
        float* qp  = out + (size_t)Q_OFF + (size_t)wid * WSZ_;

        const int a         = (-wid) & 3;       // head count to reach 16B alignment
        const int ngroups   = (WSZ_ - a) >> 2;  // 71 or 72 float4 groups
        const int tailstart = a + (ngroups << 2);
        const int tail      = WSZ_ - tailstart; // 0..3

        auto doScalar = [&](int e) {
            const int u = (e * 241) >> 12;      // e / 17 (exact for 0<=e<=288)
            const int v = e - u * 17;
            const float val = wsm[u * TILE_PAD + v];
            __stcs(swp + e, val);
            __stcs(qp  + e, floorf(val * 64.0f)); // digitize(linspace(0,1,65)) - 1
        };

        if (lane < a) doScalar(lane);

        // --- Merged pair of unconditional groups, stores ordered per-stream
        {
            const int e0 = a + 4 * lane;        // group lane
            const int e1 = e0 + 128;            // group lane+32
            float wv[8];
            #pragma unroll
            for (int tt = 0; tt < 4; tt++) {
                const int ea = e0 + tt;
                const int ua = (ea * 241) >> 12;
                wv[tt]     = wsm[ua * TILE_PAD + (ea - ua * 17)];
                const int eb = e1 + tt;
                const int ub = (eb * 241) >> 12;
                wv[4 + tt] = wsm[ub * TILE_PAD + (eb - ub * 17)];
            }
            __stcs(reinterpret_cast<float4*>(swp + e0),
                   make_float4(wv[0], wv[1], wv[2], wv[3]));
            __stcs(reinterpret_cast<float4*>(swp + e1),
                   make_float4(wv[4], wv[5], wv[6], wv[7]));
            __stcs(reinterpret_cast<float4*>(qp + e0),
                   make_float4(floorf(wv[0] * 64.0f), floorf(wv[1] * 64.0f),
                               floorf(wv[2] * 64.0f), floorf(wv[3] * 64.0f)));
            __stcs(reinterpret_cast<float4*>(qp + e1),
                   make_float4(floorf(wv[4] * 64.0f), floorf(wv[5] * 64.0f),
                               floorf(wv[6] * 64.0f), floorf(wv[7] * 64.0f)));
        }

        // --- Conditional third group (7-8 lanes)
        if (lane + 64 < ngroups) {
            const int e0 = a + 4 * (lane + 64);
            float wv[4];
            #pragma unroll
            for (int tt = 0; tt < 4; tt++) {
                const int e = e0 + tt;
                const int u = (e * 241) >> 12;
                wv[tt] = wsm[u * TILE_PAD + (e - u * 17)];
            }
            __stcs(reinterpret_cast<float4*>(swp + e0),
                   make_float4(wv[0], wv[1], wv[2], wv[3]));
            __stcs(reinterpret_cast<float4*>(qp + e0),
                   make_float4(floorf(wv[0] * 64.0f), floorf(wv[1] * 64.0f),
                               floorf(wv[2] * 64.0f), floorf(wv[3] * 64.0f)));
        }
        if (lane < tail) doScalar(tailstart + lane);
    }
}

extern "C" void kernel_launch(void* const* d_in, const int* in_sizes, int n_in,
                              void* d_out, int out_size)
{
    const float* x = (const float*)d_in[0];   // (32,3,257,257) float32
    // d_in[1] = bins (65 floats) — uniform linspace(0,1,65); digitize-1 == floor(v*64)
    float* out = (float*)d_out;

    // 10 blocks per (bc, i-pair): 8 copy j-tiles (2 i's each) + 2 stats
    const int blocks = (B_ * C_) * NIP_ * 10;  // 96 * 31 * 10 = 29760
    leafnet_kernel<<<blocks, 256>>>(x, out);
}